// round 10
// baseline (speedup 1.0000x reference)
#include <cuda_runtime.h>
#include <cuda_bf16.h>
#include <math.h>

#define TOK   4096     // B*T
#define DIMV  512
#define DQ    1024
#define NKEY  256
#define DH    128
#define NHEAD 4

// ---------------- scratch (no allocations allowed) ----------------
__device__ float g_q[TOK * DQ];          // 16 MB
__device__ float g_dots[TOK * 2048];     // 32 MB  [token][h][p][n]
__device__ float g_w[TOK * 128];
__device__ int   g_vidx[TOK * 128];

#define BM 64
#define BN 64
#define BK 16

// =================== q-proj GEMM: pure ascending fused-FMA chain (Eigen gebp order) ===================
__global__ __launch_bounds__(256) void gemm_tn_asc(
    const float* __restrict__ A, int lda,
    const float* __restrict__ B, int ldb,
    float* __restrict__ C, int ldc, int K)
{
    __shared__ float As[BK][BM];
    __shared__ float Bs[BK][BN];

    const int tid = threadIdx.x;
    const int tx = tid & 15;
    const int ty = tid >> 4;
    const int m0 = blockIdx.y * BM;
    const int n0 = blockIdx.x * BN;

    const int lrow = tid >> 2;
    const int lk   = (tid & 3) * 4;

    const float* Ab = A + (size_t)(m0 + lrow) * lda + lk;
    const float* Bb = B + (size_t)(n0 + lrow) * ldb + lk;

    float acc[4][4];
#pragma unroll
    for (int i = 0; i < 4; i++)
#pragma unroll
        for (int j = 0; j < 4; j++) acc[i][j] = 0.f;

    for (int k0 = 0; k0 < K; k0 += BK) {
        float4 va = *(const float4*)(Ab + k0);
        float4 vb = *(const float4*)(Bb + k0);
        As[lk + 0][lrow] = va.x; As[lk + 1][lrow] = va.y;
        As[lk + 2][lrow] = va.z; As[lk + 3][lrow] = va.w;
        Bs[lk + 0][lrow] = vb.x; Bs[lk + 1][lrow] = vb.y;
        Bs[lk + 2][lrow] = vb.z; Bs[lk + 3][lrow] = vb.w;
        __syncthreads();
#pragma unroll
        for (int kk = 0; kk < BK; kk++) {
            float a[4], b[4];
#pragma unroll
            for (int i = 0; i < 4; i++) a[i] = As[kk][ty * 4 + i];
#pragma unroll
            for (int j = 0; j < 4; j++) b[j] = Bs[kk][tx * 4 + j];
#pragma unroll
            for (int i = 0; i < 4; i++)
#pragma unroll
                for (int j = 0; j < 4; j++) acc[i][j] = fmaf(a[i], b[j], acc[i][j]);
        }
        __syncthreads();
    }

#pragma unroll
    for (int i = 0; i < 4; i++) {
        float* Crow = C + (size_t)(m0 + ty * 4 + i) * ldc + n0 + tx * 4;
#pragma unroll
        for (int j = 0; j < 4; j++) Crow[j] = acc[i][j];
    }
}

// =================== dots GEMM: 4 k-strided fused chains (NEON vectorized-dot order) ===================
// acc_l = sum over k ≡ l (mod 4), fused FMA chains; combine ((s0+s1)+(s2+s3)) exact adds.
__global__ __launch_bounds__(256) void gemm_tn_s4(
    const float* __restrict__ A, int lda,
    const float* __restrict__ B, int ldb,
    float* __restrict__ C, int ldc, int K)
{
    __shared__ float As[BK][BM];
    __shared__ float Bs[BK][BN];

    const int tid = threadIdx.x;
    const int tx = tid & 15;
    const int ty = tid >> 4;
    const int m0 = blockIdx.y * BM;
    const int n0 = blockIdx.x * BN;

    const int lrow = tid >> 2;
    const int lk   = (tid & 3) * 4;

    const float* Ab = A + (size_t)(m0 + lrow) * lda + lk;
    const float* Bb = B + (size_t)(n0 + lrow) * ldb + lk;

    float s[4][4][4];     // [i][j][chain]
#pragma unroll
    for (int i = 0; i < 4; i++)
#pragma unroll
        for (int j = 0; j < 4; j++)
#pragma unroll
            for (int c = 0; c < 4; c++) s[i][j][c] = 0.f;

    for (int k0 = 0; k0 < K; k0 += BK) {
        float4 va = *(const float4*)(Ab + k0);
        float4 vb = *(const float4*)(Bb + k0);
        As[lk + 0][lrow] = va.x; As[lk + 1][lrow] = va.y;
        As[lk + 2][lrow] = va.z; As[lk + 3][lrow] = va.w;
        Bs[lk + 0][lrow] = vb.x; Bs[lk + 1][lrow] = vb.y;
        Bs[lk + 2][lrow] = vb.z; Bs[lk + 3][lrow] = vb.w;
        __syncthreads();
#pragma unroll
        for (int kk = 0; kk < BK; kk++) {
            const int ch = kk & 3;
            float a[4], b[4];
#pragma unroll
            for (int i = 0; i < 4; i++) a[i] = As[kk][ty * 4 + i];
#pragma unroll
            for (int j = 0; j < 4; j++) b[j] = Bs[kk][tx * 4 + j];
#pragma unroll
            for (int i = 0; i < 4; i++)
#pragma unroll
                for (int j = 0; j < 4; j++)
                    s[i][j][ch] = fmaf(a[i], b[j], s[i][j][ch]);
        }
        __syncthreads();
    }

#pragma unroll
    for (int i = 0; i < 4; i++) {
        float* Crow = C + (size_t)(m0 + ty * 4 + i) * ldc + n0 + tx * 4;
#pragma unroll
        for (int j = 0; j < 4; j++) {
            float p01 = __fadd_rn(s[i][j][0], s[i][j][1]);
            float p23 = __fadd_rn(s[i][j][2], s[i][j][3]);
            Crow[j] = __fadd_rn(p01, p23);
        }
    }
}

// =================== LayerNorm: sequential fp32, non-fused (proven neutral) ===================
#define LN_ROWS 64

__global__ __launch_bounds__(LN_ROWS) void ln_kernel(
    float* __restrict__ q, const float* __restrict__ g, const float* __restrict__ b)
{
    __shared__ float sm[LN_ROWS * 129];
    __shared__ float sg[128], sb[128];
    const int t = threadIdx.x;
    const size_t base = (size_t)blockIdx.x * LN_ROWS * 128;

    for (int i = t; i < LN_ROWS * 128; i += LN_ROWS) {
        int r = i >> 7, c = i & 127;
        sm[r * 129 + c] = q[base + i];
    }
    for (int i = t; i < 128; i += LN_ROWS) { sg[i] = g[i]; sb[i] = b[i]; }
    __syncthreads();

    float* row = sm + t * 129;
    float s = 0.f;
#pragma unroll 8
    for (int i = 0; i < 128; i++) s = __fadd_rn(s, row[i]);
    const float mu = __fdiv_rn(s, 128.0f);

    float ss = 0.f;
#pragma unroll 8
    for (int i = 0; i < 128; i++) {
        float d = __fadd_rn(row[i], -mu);
        ss = __fadd_rn(ss, __fmul_rn(d, d));
    }
    const float var = __fdiv_rn(ss, 128.0f);
    const float r = __fdiv_rn(1.0f, sqrtf(__fadd_rn(var, 1e-5f)));

#pragma unroll 8
    for (int i = 0; i < 128; i++) {
        float d = __fadd_rn(row[i], -mu);
        row[i] = __fadd_rn(__fmul_rn(__fmul_rn(d, r), sg[i]), sb[i]);
    }
    __syncthreads();

    for (int i = t; i < LN_ROWS * 128; i += LN_ROWS) {
        int r2 = i >> 7, c = i & 127;
        q[base + i] = sm[r2 * 129 + c];
    }
}

// =================== top-k machinery ===================
__device__ __forceinline__ unsigned int fkey(float f) {
    unsigned int u = __float_as_uint(f);
    return (u & 0x80000000u) ? ~u : (u | 0x80000000u);
}
__device__ __forceinline__ float finv(unsigned int u) {
    unsigned int b = (u & 0x80000000u) ? (u ^ 0x80000000u) : ~u;
    return __uint_as_float(b);
}
__device__ __forceinline__ unsigned long long warp_max_ull(unsigned long long k) {
#pragma unroll
    for (int off = 16; off; off >>= 1) {
        unsigned long long o = __shfl_xor_sync(0xFFFFFFFFu, k, off);
        if (o > k) k = o;
    }
    return k;
}

#define CSWAP(a, b) { if (k[b] > k[a]) { unsigned long long t = k[a]; k[a] = k[b]; k[b] = t; } }
#define SORT8_DESC() \
    CSWAP(0,1) CSWAP(2,3) CSWAP(4,5) CSWAP(6,7) \
    CSWAP(0,2) CSWAP(1,3) CSWAP(4,6) CSWAP(5,7) \
    CSWAP(1,2) CSWAP(5,6) CSWAP(0,4) CSWAP(3,7) \
    CSWAP(1,5) CSWAP(2,6) \
    CSWAP(1,4) CSWAP(3,6) \
    CSWAP(2,4) CSWAP(3,5) \
    CSWAP(3,4)

__device__ __forceinline__ void top32_of_256(
    const float* __restrict__ d, int lane, unsigned long long* __restrict__ sm,
    float& selv, int& seli)
{
    unsigned long long k[8];
#pragma unroll
    for (int r = 0; r < 8; r++) {
        int n = r * 32 + lane;
        k[r] = (((unsigned long long)fkey(d[n])) << 32) | (unsigned int)(~(unsigned int)n);
    }
    SORT8_DESC();
#pragma unroll
    for (int r = 0; r < 8; r++) sm[lane * 8 + r] = k[r];
    __syncwarp();

    int ptr = 0;
    float sv = 0.f; int si = 0;
    for (int i = 0; i < 32; i++) {
        unsigned long long h = (ptr < 8) ? sm[lane * 8 + ptr] : 0ULL;
        unsigned long long m = warp_max_ull(h);
        unsigned int n = ~(unsigned int)m;
        if (lane == (int)(n & 31u)) ptr++;
        if (lane == i) { sv = finv((unsigned int)(m >> 32)); si = (int)n; }
    }
    __syncwarp();
    selv = sv; seli = si;
}

__global__ __launch_bounds__(128) void topk_kernel(
    const float* __restrict__ dots, float* __restrict__ wout, int* __restrict__ vout)
{
    const int token = blockIdx.x;
    const int wid = threadIdx.x >> 5;
    const int lane = threadIdx.x & 31;

    __shared__ unsigned long long ssm[4][256];

    const float* dx = dots + (size_t)token * 2048 + wid * 512;
    const float* dy = dx + 256;

    float sxv, syv; int sxi, syi;
    top32_of_256(dx, lane, ssm[wid], sxv, sxi);
    top32_of_256(dy, lane, ssm[wid], syv, syi);

    int pj = 0;
    float fsv = 0.f; int fvidx = 0;
    for (int i = 0; i < 32; i++) {
        int src = (pj < 32) ? pj : 31;
        float sxp = __shfl_sync(0xFFFFFFFFu, sxv, src);
        float cand = __fadd_rn(sxp, syv);
        unsigned int flat = (unsigned int)(pj * 32 + lane);
        unsigned long long key = (pj < 32)
            ? ((((unsigned long long)fkey(cand)) << 32) | (unsigned int)(1023u - flat))
            : 0ULL;
        unsigned long long m = warp_max_ull(key);
        unsigned int fl = 1023u - (unsigned int)m;
        int wi = (int)(fl >> 5), wj = (int)(fl & 31u);
        int ixv = __shfl_sync(0xFFFFFFFFu, sxi, wi);
        int iyv = __shfl_sync(0xFFFFFFFFu, syi, wj);
        if (lane == wj) pj++;
        if (lane == i) { fsv = finv((unsigned int)(m >> 32)); fvidx = ixv * 256 + iyv; }
    }

    const float mx = __shfl_sync(0xFFFFFFFFu, fsv, 0);
    const float e = expf(__fadd_rn(fsv, -mx));
    float ssum = e;
#pragma unroll
    for (int off = 16; off; off >>= 1) ssum += __shfl_xor_sync(0xFFFFFFFFu, ssum, off);
    const float w = __fdiv_rn(e, ssum);

    const int base = (token * 4 + wid) * 32 + lane;
    wout[base] = w;
    vout[base] = fvidx;
}

// =================== weighted gather: ascending fused chain ===================
__global__ __launch_bounds__(128) void gather_kernel(
    const float* __restrict__ values, const float* __restrict__ w,
    const int* __restrict__ vidx, float* __restrict__ out)
{
    const int token = blockIdx.x;
    const int t = threadIdx.x;
    __shared__ float sw[128];
    __shared__ int   si[128];
    sw[t] = w[(size_t)token * 128 + t];
    si[t] = vidx[(size_t)token * 128 + t];
    __syncthreads();

    float4 acc = make_float4(0.f, 0.f, 0.f, 0.f);
#pragma unroll 4
    for (int r = 0; r < 128; r++) {
        const float4* row = (const float4*)(values + (size_t)si[r] * 512);
        float4 v = __ldg(&row[t]);
        float wr = sw[r];
        acc.x = fmaf(wr, v.x, acc.x); acc.y = fmaf(wr, v.y, acc.y);
        acc.z = fmaf(wr, v.z, acc.z); acc.w = fmaf(wr, v.w, acc.w);
    }
    ((float4*)(out + (size_t)token * 512))[t] = acc;
}

// =================== launcher ===================
extern "C" void kernel_launch(void* const* d_in, const int* in_sizes, int n_in,
                              void* d_out, int out_size)
{
    const float* x      = (const float*)d_in[0];   // (2,2048,512)
    const float* wq     = (const float*)d_in[1];   // (1024,512)
    const float* ln_g   = (const float*)d_in[2];   // (128,)
    const float* ln_b   = (const float*)d_in[3];   // (128,)
    const float* keys   = (const float*)d_in[4];   // (4,256,2,128)
    const float* values = (const float*)d_in[5];   // (65536,512)
    float* out = (float*)d_out;

    float *qp, *dp, *wp; int* ip;
    cudaGetSymbolAddress((void**)&qp, g_q);
    cudaGetSymbolAddress((void**)&dp, g_dots);
    cudaGetSymbolAddress((void**)&wp, g_w);
    cudaGetSymbolAddress((void**)&ip, g_vidx);

    // 1) q = x @ wq^T : ascending fused chain (Eigen gebp emulation)
    gemm_tn_asc<<<dim3(DQ / BN, TOK / BM), 256>>>(x, DIMV, wq, DIMV, qp, DQ, DIMV);

    // 2) layernorm per 128-vector (in place)
    ln_kernel<<<(TOK * 8) / LN_ROWS, LN_ROWS>>>(qp, ln_g, ln_b);

    // 3) dots: 8 slices of (4096 x 256 x 128), 4 k-strided chains (NEON dot emulation)
    for (int z = 0; z < 8; z++) {
        int h = z >> 1, p = z & 1;
        gemm_tn_s4<<<dim3(NKEY / BN, TOK / BM), 256>>>(
            qp + (p * 4 + h) * 128, DQ,
            keys + h * (NKEY * 2 * DH) + p * DH, 2 * DH,
            dp + h * 512 + p * 256, 2048, DH);
    }

    // 4) top-k + combine + softmax
    topk_kernel<<<TOK, 128>>>(dp, wp, ip);

    // 5) weighted value gather
    gather_kernel<<<TOK, 128>>>(values, wp, ip, out);
}

// round 11
// speedup vs baseline: 1.1405x; 1.1405x over previous
#include <cuda_runtime.h>
#include <cuda_bf16.h>
#include <math.h>

#define TOK   4096     // B*T
#define DIMV  512
#define DQ    1024
#define NKEY  256
#define DH    128
#define NHEAD 4

// ---------------- scratch (no allocations allowed) ----------------
__device__ float g_q[TOK * DQ];          // 16 MB
__device__ float g_dots[TOK * 2048];     // 32 MB  [token][h][p][n]
__device__ float g_w[TOK * 128];
__device__ int   g_vidx[TOK * 128];

// =================== q-proj GEMM: 128x128 tile, 8x8/thread, ascending fused-FMA chain ===================
// Per-output accumulation order: k ascending, single fused chain (bit-identical to R10 pass).
#define QBM 128
#define QBN 128
#define QBK 16

__global__ __launch_bounds__(256) void gemm_asc_128(
    const float* __restrict__ A, int lda,
    const float* __restrict__ B, int ldb,
    float* __restrict__ C, int ldc, int K)
{
    __shared__ float As[QBK][132];
    __shared__ float Bs[QBK][132];

    const int tid = threadIdx.x;
    const int tx = tid & 15;            // n subtile
    const int ty = tid >> 4;            // m subtile
    const int m0 = blockIdx.y * QBM;
    const int n0 = blockIdx.x * QBN;

    const int lrow = tid >> 1;          // 0..127
    const int lk   = (tid & 1) * 8;     // 0 or 8

    const float* Ab = A + (size_t)(m0 + lrow) * lda + lk;
    const float* Bb = B + (size_t)(n0 + lrow) * ldb + lk;

    float acc[8][8];
#pragma unroll
    for (int i = 0; i < 8; i++)
#pragma unroll
        for (int j = 0; j < 8; j++) acc[i][j] = 0.f;

    // prefetch first tile
    float4 va0 = *(const float4*)(Ab);
    float4 va1 = *(const float4*)(Ab + 4);
    float4 vb0 = *(const float4*)(Bb);
    float4 vb1 = *(const float4*)(Bb + 4);

    for (int k0 = 0; k0 < K; k0 += QBK) {
        As[lk + 0][lrow] = va0.x; As[lk + 1][lrow] = va0.y;
        As[lk + 2][lrow] = va0.z; As[lk + 3][lrow] = va0.w;
        As[lk + 4][lrow] = va1.x; As[lk + 5][lrow] = va1.y;
        As[lk + 6][lrow] = va1.z; As[lk + 7][lrow] = va1.w;
        Bs[lk + 0][lrow] = vb0.x; Bs[lk + 1][lrow] = vb0.y;
        Bs[lk + 2][lrow] = vb0.z; Bs[lk + 3][lrow] = vb0.w;
        Bs[lk + 4][lrow] = vb1.x; Bs[lk + 5][lrow] = vb1.y;
        Bs[lk + 6][lrow] = vb1.z; Bs[lk + 7][lrow] = vb1.w;
        __syncthreads();

        if (k0 + QBK < K) {     // prefetch next tile while computing
            va0 = *(const float4*)(Ab + k0 + QBK);
            va1 = *(const float4*)(Ab + k0 + QBK + 4);
            vb0 = *(const float4*)(Bb + k0 + QBK);
            vb1 = *(const float4*)(Bb + k0 + QBK + 4);
        }

#pragma unroll
        for (int kk = 0; kk < QBK; kk++) {
            float a[8], b[8];
            *(float4*)(a)     = *(const float4*)(&As[kk][ty * 8]);
            *(float4*)(a + 4) = *(const float4*)(&As[kk][ty * 8 + 4]);
            *(float4*)(b)     = *(const float4*)(&Bs[kk][tx * 8]);
            *(float4*)(b + 4) = *(const float4*)(&Bs[kk][tx * 8 + 4]);
#pragma unroll
            for (int i = 0; i < 8; i++)
#pragma unroll
                for (int j = 0; j < 8; j++)
                    acc[i][j] = fmaf(a[i], b[j], acc[i][j]);   // ascending fused chain
        }
        __syncthreads();
    }

#pragma unroll
    for (int i = 0; i < 8; i++) {
        float* Crow = C + (size_t)(m0 + ty * 8 + i) * ldc + n0 + tx * 8;
        *(float4*)(Crow)     = make_float4(acc[i][0], acc[i][1], acc[i][2], acc[i][3]);
        *(float4*)(Crow + 4) = make_float4(acc[i][4], acc[i][5], acc[i][6], acc[i][7]);
    }
}

// =================== dots GEMM: 4 k-strided fused chains, z-batched over 8 (h,p) slices ===================
#define BM 64
#define BN 64
#define BK 16

__global__ __launch_bounds__(256) void gemm_dots_s4(
    const float* __restrict__ qbuf, const float* __restrict__ keys,
    float* __restrict__ dots)
{
    const int z = blockIdx.z;
    const int h = z >> 1, p = z & 1;
    const float* A = qbuf + (p * 4 + h) * 128;             // lda = DQ
    const float* B = keys + h * (NKEY * 2 * DH) + p * DH;  // ldb = 2*DH
    float* C = dots + h * 512 + p * 256;                   // ldc = 2048
    const int lda = DQ, ldb = 2 * DH, ldc = 2048, K = DH;

    __shared__ float As[BK][BM];
    __shared__ float Bs[BK][BN];

    const int tid = threadIdx.x;
    const int tx = tid & 15;
    const int ty = tid >> 4;
    const int m0 = blockIdx.y * BM;
    const int n0 = blockIdx.x * BN;

    const int lrow = tid >> 2;
    const int lk   = (tid & 3) * 4;

    const float* Ab = A + (size_t)(m0 + lrow) * lda + lk;
    const float* Bb = B + (size_t)(n0 + lrow) * ldb + lk;

    float s[4][4][4];     // [i][j][chain]
#pragma unroll
    for (int i = 0; i < 4; i++)
#pragma unroll
        for (int j = 0; j < 4; j++)
#pragma unroll
            for (int c = 0; c < 4; c++) s[i][j][c] = 0.f;

    for (int k0 = 0; k0 < K; k0 += BK) {
        float4 va = *(const float4*)(Ab + k0);
        float4 vb = *(const float4*)(Bb + k0);
        As[lk + 0][lrow] = va.x; As[lk + 1][lrow] = va.y;
        As[lk + 2][lrow] = va.z; As[lk + 3][lrow] = va.w;
        Bs[lk + 0][lrow] = vb.x; Bs[lk + 1][lrow] = vb.y;
        Bs[lk + 2][lrow] = vb.z; Bs[lk + 3][lrow] = vb.w;
        __syncthreads();
#pragma unroll
        for (int kk = 0; kk < BK; kk++) {
            const int ch = kk & 3;
            float a[4], b[4];
#pragma unroll
            for (int i = 0; i < 4; i++) a[i] = As[kk][ty * 4 + i];
#pragma unroll
            for (int j = 0; j < 4; j++) b[j] = Bs[kk][tx * 4 + j];
#pragma unroll
            for (int i = 0; i < 4; i++)
#pragma unroll
                for (int j = 0; j < 4; j++)
                    s[i][j][ch] = fmaf(a[i], b[j], s[i][j][ch]);
        }
        __syncthreads();
    }

#pragma unroll
    for (int i = 0; i < 4; i++) {
        float* Crow = C + (size_t)(m0 + ty * 4 + i) * ldc + n0 + tx * 4;
#pragma unroll
        for (int j = 0; j < 4; j++) {
            float p01 = __fadd_rn(s[i][j][0], s[i][j][1]);
            float p23 = __fadd_rn(s[i][j][2], s[i][j][3]);
            Crow[j] = __fadd_rn(p01, p23);
        }
    }
}

// =================== LayerNorm: sequential fp32, non-fused (proven neutral) ===================
#define LN_ROWS 64

__global__ __launch_bounds__(LN_ROWS) void ln_kernel(
    float* __restrict__ q, const float* __restrict__ g, const float* __restrict__ b)
{
    __shared__ float sm[LN_ROWS * 129];
    __shared__ float sg[128], sb[128];
    const int t = threadIdx.x;
    const size_t base = (size_t)blockIdx.x * LN_ROWS * 128;

    for (int i = t; i < LN_ROWS * 128; i += LN_ROWS) {
        int r = i >> 7, c = i & 127;
        sm[r * 129 + c] = q[base + i];
    }
    for (int i = t; i < 128; i += LN_ROWS) { sg[i] = g[i]; sb[i] = b[i]; }
    __syncthreads();

    float* row = sm + t * 129;
    float s = 0.f;
#pragma unroll 8
    for (int i = 0; i < 128; i++) s = __fadd_rn(s, row[i]);
    const float mu = __fdiv_rn(s, 128.0f);

    float ss = 0.f;
#pragma unroll 8
    for (int i = 0; i < 128; i++) {
        float d = __fadd_rn(row[i], -mu);
        ss = __fadd_rn(ss, __fmul_rn(d, d));
    }
    const float var = __fdiv_rn(ss, 128.0f);
    const float r = __fdiv_rn(1.0f, sqrtf(__fadd_rn(var, 1e-5f)));

#pragma unroll 8
    for (int i = 0; i < 128; i++) {
        float d = __fadd_rn(row[i], -mu);
        row[i] = __fadd_rn(__fmul_rn(__fmul_rn(d, r), sg[i]), sb[i]);
    }
    __syncthreads();

    for (int i = t; i < LN_ROWS * 128; i += LN_ROWS) {
        int r2 = i >> 7, c = i & 127;
        q[base + i] = sm[r2 * 129 + c];
    }
}

// =================== top-k machinery ===================
__device__ __forceinline__ unsigned int fkey(float f) {
    unsigned int u = __float_as_uint(f);
    return (u & 0x80000000u) ? ~u : (u | 0x80000000u);
}
__device__ __forceinline__ float finv(unsigned int u) {
    unsigned int b = (u & 0x80000000u) ? (u ^ 0x80000000u) : ~u;
    return __uint_as_float(b);
}
__device__ __forceinline__ unsigned long long warp_max_ull(unsigned long long k) {
#pragma unroll
    for (int off = 16; off; off >>= 1) {
        unsigned long long o = __shfl_xor_sync(0xFFFFFFFFu, k, off);
        if (o > k) k = o;
    }
    return k;
}

#define CSWAP(a, b) { if (k[b] > k[a]) { unsigned long long t = k[a]; k[a] = k[b]; k[b] = t; } }
#define SORT8_DESC() \
    CSWAP(0,1) CSWAP(2,3) CSWAP(4,5) CSWAP(6,7) \
    CSWAP(0,2) CSWAP(1,3) CSWAP(4,6) CSWAP(5,7) \
    CSWAP(1,2) CSWAP(5,6) CSWAP(0,4) CSWAP(3,7) \
    CSWAP(1,5) CSWAP(2,6) \
    CSWAP(1,4) CSWAP(3,6) \
    CSWAP(2,4) CSWAP(3,5) \
    CSWAP(3,4)

__device__ __forceinline__ void top32_of_256(
    const float* __restrict__ d, int lane, unsigned long long* __restrict__ sm,
    float& selv, int& seli)
{
    unsigned long long k[8];
#pragma unroll
    for (int r = 0; r < 8; r++) {
        int n = r * 32 + lane;
        k[r] = (((unsigned long long)fkey(d[n])) << 32) | (unsigned int)(~(unsigned int)n);
    }
    SORT8_DESC();
#pragma unroll
    for (int r = 0; r < 8; r++) sm[lane * 8 + r] = k[r];
    __syncwarp();

    int ptr = 0;
    float sv = 0.f; int si = 0;
    for (int i = 0; i < 32; i++) {
        unsigned long long h = (ptr < 8) ? sm[lane * 8 + ptr] : 0ULL;
        unsigned long long m = warp_max_ull(h);
        unsigned int n = ~(unsigned int)m;
        if (lane == (int)(n & 31u)) ptr++;
        if (lane == i) { sv = finv((unsigned int)(m >> 32)); si = (int)n; }
    }
    __syncwarp();
    selv = sv; seli = si;
}

__global__ __launch_bounds__(128) void topk_kernel(
    const float* __restrict__ dots, float* __restrict__ wout, int* __restrict__ vout)
{
    const int token = blockIdx.x;
    const int wid = threadIdx.x >> 5;
    const int lane = threadIdx.x & 31;

    __shared__ unsigned long long ssm[4][256];

    const float* dx = dots + (size_t)token * 2048 + wid * 512;
    const float* dy = dx + 256;

    float sxv, syv; int sxi, syi;
    top32_of_256(dx, lane, ssm[wid], sxv, sxi);
    top32_of_256(dy, lane, ssm[wid], syv, syi);

    int pj = 0;
    float fsv = 0.f; int fvidx = 0;
    for (int i = 0; i < 32; i++) {
        int src = (pj < 32) ? pj : 31;
        float sxp = __shfl_sync(0xFFFFFFFFu, sxv, src);
        float cand = __fadd_rn(sxp, syv);
        unsigned int flat = (unsigned int)(pj * 32 + lane);
        unsigned long long key = (pj < 32)
            ? ((((unsigned long long)fkey(cand)) << 32) | (unsigned int)(1023u - flat))
            : 0ULL;
        unsigned long long m = warp_max_ull(key);
        unsigned int fl = 1023u - (unsigned int)m;
        int wi = (int)(fl >> 5), wj = (int)(fl & 31u);
        int ixv = __shfl_sync(0xFFFFFFFFu, sxi, wi);
        int iyv = __shfl_sync(0xFFFFFFFFu, syi, wj);
        if (lane == wj) pj++;
        if (lane == i) { fsv = finv((unsigned int)(m >> 32)); fvidx = ixv * 256 + iyv; }
    }

    const float mx = __shfl_sync(0xFFFFFFFFu, fsv, 0);
    const float e = expf(__fadd_rn(fsv, -mx));
    float ssum = e;
#pragma unroll
    for (int off = 16; off; off >>= 1) ssum += __shfl_xor_sync(0xFFFFFFFFu, ssum, off);
    const float w = __fdiv_rn(e, ssum);

    const int base = (token * 4 + wid) * 32 + lane;
    wout[base] = w;
    vout[base] = fvidx;
}

// =================== weighted gather: ascending fused chain ===================
__global__ __launch_bounds__(128) void gather_kernel(
    const float* __restrict__ values, const float* __restrict__ w,
    const int* __restrict__ vidx, float* __restrict__ out)
{
    const int token = blockIdx.x;
    const int t = threadIdx.x;
    __shared__ float sw[128];
    __shared__ int   si[128];
    sw[t] = w[(size_t)token * 128 + t];
    si[t] = vidx[(size_t)token * 128 + t];
    __syncthreads();

    float4 acc = make_float4(0.f, 0.f, 0.f, 0.f);
#pragma unroll 8
    for (int r = 0; r < 128; r++) {
        const float4* row = (const float4*)(values + (size_t)si[r] * 512);
        float4 v = __ldg(&row[t]);
        float wr = sw[r];
        acc.x = fmaf(wr, v.x, acc.x); acc.y = fmaf(wr, v.y, acc.y);
        acc.z = fmaf(wr, v.z, acc.z); acc.w = fmaf(wr, v.w, acc.w);
    }
    ((float4*)(out + (size_t)token * 512))[t] = acc;
}

// =================== launcher ===================
extern "C" void kernel_launch(void* const* d_in, const int* in_sizes, int n_in,
                              void* d_out, int out_size)
{
    const float* x      = (const float*)d_in[0];   // (2,2048,512)
    const float* wq     = (const float*)d_in[1];   // (1024,512)
    const float* ln_g   = (const float*)d_in[2];   // (128,)
    const float* ln_b   = (const float*)d_in[3];   // (128,)
    const float* keys   = (const float*)d_in[4];   // (4,256,2,128)
    const float* values = (const float*)d_in[5];   // (65536,512)
    float* out = (float*)d_out;

    float *qp, *dp, *wp; int* ip;
    cudaGetSymbolAddress((void**)&qp, g_q);
    cudaGetSymbolAddress((void**)&dp, g_dots);
    cudaGetSymbolAddress((void**)&wp, g_w);
    cudaGetSymbolAddress((void**)&ip, g_vidx);

    // 1) q = x @ wq^T : ascending fused chain, 128x128 tiles
    gemm_asc_128<<<dim3(DQ / QBN, TOK / QBM), 256>>>(x, DIMV, wq, DIMV, qp, DQ, DIMV);

    // 2) layernorm per 128-vector (in place)
    ln_kernel<<<(TOK * 8) / LN_ROWS, LN_ROWS>>>(qp, ln_g, ln_b);

    // 3) dots: all 8 (h,p) slices in one launch, 4 k-strided chains
    gemm_dots_s4<<<dim3(NKEY / BN, TOK / BM, 8), 256>>>(qp, keys, dp);

    // 4) top-k + combine + softmax
    topk_kernel<<<TOK, 128>>>(dp, wp, ip);

    // 5) weighted value gather
    gather_kernel<<<TOK, 128>>>(values, wp, ip, out);
}

// round 12
// speedup vs baseline: 1.2822x; 1.1242x over previous
#include <cuda_runtime.h>
#include <cuda_bf16.h>
#include <math.h>

#define TOK   4096     // B*T
#define DIMV  512
#define DQ    1024
#define NKEY  256
#define DH    128
#define NHEAD 4

// ---------------- scratch (no allocations allowed) ----------------
__device__ float g_q[TOK * DQ];          // 16 MB
__device__ float g_dots[TOK * 2048];     // 32 MB  [token][h][p][n]
__device__ float g_w[TOK * 128];
__device__ int   g_vidx[TOK * 128];

// =================== q-proj GEMM: 128x128 tile, 8x8/thread, ascending fused-FMA chain ===================
#define QBM 128
#define QBN 128
#define QBK 16

__global__ __launch_bounds__(256) void gemm_asc_128(
    const float* __restrict__ A, int lda,
    const float* __restrict__ B, int ldb,
    float* __restrict__ C, int ldc, int K)
{
    __shared__ float As[QBK][132];
    __shared__ float Bs[QBK][132];

    const int tid = threadIdx.x;
    const int tx = tid & 15;
    const int ty = tid >> 4;
    const int m0 = blockIdx.y * QBM;
    const int n0 = blockIdx.x * QBN;

    const int lrow = tid >> 1;
    const int lk   = (tid & 1) * 8;

    const float* Ab = A + (size_t)(m0 + lrow) * lda + lk;
    const float* Bb = B + (size_t)(n0 + lrow) * ldb + lk;

    float acc[8][8];
#pragma unroll
    for (int i = 0; i < 8; i++)
#pragma unroll
        for (int j = 0; j < 8; j++) acc[i][j] = 0.f;

    float4 va0 = *(const float4*)(Ab);
    float4 va1 = *(const float4*)(Ab + 4);
    float4 vb0 = *(const float4*)(Bb);
    float4 vb1 = *(const float4*)(Bb + 4);

    for (int k0 = 0; k0 < K; k0 += QBK) {
        As[lk + 0][lrow] = va0.x; As[lk + 1][lrow] = va0.y;
        As[lk + 2][lrow] = va0.z; As[lk + 3][lrow] = va0.w;
        As[lk + 4][lrow] = va1.x; As[lk + 5][lrow] = va1.y;
        As[lk + 6][lrow] = va1.z; As[lk + 7][lrow] = va1.w;
        Bs[lk + 0][lrow] = vb0.x; Bs[lk + 1][lrow] = vb0.y;
        Bs[lk + 2][lrow] = vb0.z; Bs[lk + 3][lrow] = vb0.w;
        Bs[lk + 4][lrow] = vb1.x; Bs[lk + 5][lrow] = vb1.y;
        Bs[lk + 6][lrow] = vb1.z; Bs[lk + 7][lrow] = vb1.w;
        __syncthreads();

        if (k0 + QBK < K) {
            va0 = *(const float4*)(Ab + k0 + QBK);
            va1 = *(const float4*)(Ab + k0 + QBK + 4);
            vb0 = *(const float4*)(Bb + k0 + QBK);
            vb1 = *(const float4*)(Bb + k0 + QBK + 4);
        }

#pragma unroll
        for (int kk = 0; kk < QBK; kk++) {
            float a[8], b[8];
            *(float4*)(a)     = *(const float4*)(&As[kk][ty * 8]);
            *(float4*)(a + 4) = *(const float4*)(&As[kk][ty * 8 + 4]);
            *(float4*)(b)     = *(const float4*)(&Bs[kk][tx * 8]);
            *(float4*)(b + 4) = *(const float4*)(&Bs[kk][tx * 8 + 4]);
#pragma unroll
            for (int i = 0; i < 8; i++)
#pragma unroll
                for (int j = 0; j < 8; j++)
                    acc[i][j] = fmaf(a[i], b[j], acc[i][j]);   // ascending fused chain
        }
        __syncthreads();
    }

#pragma unroll
    for (int i = 0; i < 8; i++) {
        float* Crow = C + (size_t)(m0 + ty * 8 + i) * ldc + n0 + tx * 8;
        *(float4*)(Crow)     = make_float4(acc[i][0], acc[i][1], acc[i][2], acc[i][3]);
        *(float4*)(Crow + 4) = make_float4(acc[i][4], acc[i][5], acc[i][6], acc[i][7]);
    }
}

// =================== dots GEMM: 4 k-strided fused chains, z-batched over 8 (h,p) slices ===================
#define BM 64
#define BN 64
#define BK 16

__global__ __launch_bounds__(256) void gemm_dots_s4(
    const float* __restrict__ qbuf, const float* __restrict__ keys,
    float* __restrict__ dots)
{
    const int z = blockIdx.z;
    const int h = z >> 1, p = z & 1;
    const float* A = qbuf + (p * 4 + h) * 128;
    const float* B = keys + h * (NKEY * 2 * DH) + p * DH;
    float* C = dots + h * 512 + p * 256;
    const int lda = DQ, ldb = 2 * DH, ldc = 2048, K = DH;

    __shared__ float As[BK][BM];
    __shared__ float Bs[BK][BN];

    const int tid = threadIdx.x;
    const int tx = tid & 15;
    const int ty = tid >> 4;
    const int m0 = blockIdx.y * BM;
    const int n0 = blockIdx.x * BN;

    const int lrow = tid >> 2;
    const int lk   = (tid & 3) * 4;

    const float* Ab = A + (size_t)(m0 + lrow) * lda + lk;
    const float* Bb = B + (size_t)(n0 + lrow) * ldb + lk;

    float s[4][4][4];
#pragma unroll
    for (int i = 0; i < 4; i++)
#pragma unroll
        for (int j = 0; j < 4; j++)
#pragma unroll
            for (int c = 0; c < 4; c++) s[i][j][c] = 0.f;

    for (int k0 = 0; k0 < K; k0 += BK) {
        float4 va = *(const float4*)(Ab + k0);
        float4 vb = *(const float4*)(Bb + k0);
        As[lk + 0][lrow] = va.x; As[lk + 1][lrow] = va.y;
        As[lk + 2][lrow] = va.z; As[lk + 3][lrow] = va.w;
        Bs[lk + 0][lrow] = vb.x; Bs[lk + 1][lrow] = vb.y;
        Bs[lk + 2][lrow] = vb.z; Bs[lk + 3][lrow] = vb.w;
        __syncthreads();
#pragma unroll
        for (int kk = 0; kk < BK; kk++) {
            const int ch = kk & 3;
            float a[4], b[4];
#pragma unroll
            for (int i = 0; i < 4; i++) a[i] = As[kk][ty * 4 + i];
#pragma unroll
            for (int j = 0; j < 4; j++) b[j] = Bs[kk][tx * 4 + j];
#pragma unroll
            for (int i = 0; i < 4; i++)
#pragma unroll
                for (int j = 0; j < 4; j++)
                    s[i][j][ch] = fmaf(a[i], b[j], s[i][j][ch]);
        }
        __syncthreads();
    }

#pragma unroll
    for (int i = 0; i < 4; i++) {
        float* Crow = C + (size_t)(m0 + ty * 4 + i) * ldc + n0 + tx * 4;
#pragma unroll
        for (int j = 0; j < 4; j++) {
            float p01 = __fadd_rn(s[i][j][0], s[i][j][1]);
            float p23 = __fadd_rn(s[i][j][2], s[i][j][3]);
            Crow[j] = __fadd_rn(p01, p23);
        }
    }
}

// =================== LayerNorm: sequential fp32, non-fused (proven neutral) ===================
#define LN_ROWS 64

__global__ __launch_bounds__(LN_ROWS) void ln_kernel(
    float* __restrict__ q, const float* __restrict__ g, const float* __restrict__ b)
{
    __shared__ float sm[LN_ROWS * 129];
    __shared__ float sg[128], sb[128];
    const int t = threadIdx.x;
    const size_t base = (size_t)blockIdx.x * LN_ROWS * 128;

    for (int i = t; i < LN_ROWS * 128; i += LN_ROWS) {
        int r = i >> 7, c = i & 127;
        sm[r * 129 + c] = q[base + i];
    }
    for (int i = t; i < 128; i += LN_ROWS) { sg[i] = g[i]; sb[i] = b[i]; }
    __syncthreads();

    float* row = sm + t * 129;
    float s = 0.f;
#pragma unroll 8
    for (int i = 0; i < 128; i++) s = __fadd_rn(s, row[i]);
    const float mu = __fdiv_rn(s, 128.0f);

    float ss = 0.f;
#pragma unroll 8
    for (int i = 0; i < 128; i++) {
        float d = __fadd_rn(row[i], -mu);
        ss = __fadd_rn(ss, __fmul_rn(d, d));
    }
    const float var = __fdiv_rn(ss, 128.0f);
    const float r = __fdiv_rn(1.0f, sqrtf(__fadd_rn(var, 1e-5f)));

#pragma unroll 8
    for (int i = 0; i < 128; i++) {
        float d = __fadd_rn(row[i], -mu);
        row[i] = __fadd_rn(__fmul_rn(__fmul_rn(d, r), sg[i]), sb[i]);
    }
    __syncthreads();

    for (int i = t; i < LN_ROWS * 128; i += LN_ROWS) {
        int r2 = i >> 7, c = i & 127;
        q[base + i] = sm[r2 * 129 + c];
    }
}

// =================== top-k machinery ===================
__device__ __forceinline__ unsigned int fkey(float f) {
    unsigned int u = __float_as_uint(f);
    return (u & 0x80000000u) ? ~u : (u | 0x80000000u);
}
__device__ __forceinline__ float finv(unsigned int u) {
    unsigned int b = (u & 0x80000000u) ? (u ^ 0x80000000u) : ~u;
    return __uint_as_float(b);
}

#define CSWAP(a, b) { if (k[b] > k[a]) { unsigned long long t = k[a]; k[a] = k[b]; k[b] = t; } }
#define SORT8_DESC() \
    CSWAP(0,1) CSWAP(2,3) CSWAP(4,5) CSWAP(6,7) \
    CSWAP(0,2) CSWAP(1,3) CSWAP(4,6) CSWAP(5,7) \
    CSWAP(1,2) CSWAP(5,6) CSWAP(0,4) CSWAP(3,7) \
    CSWAP(1,5) CSWAP(2,6) \
    CSWAP(1,4) CSWAP(3,6) \
    CSWAP(2,4) CSWAP(3,5) \
    CSWAP(3,4)

// warp-collective: top-32 of 256 values, REDUX-based extraction.
// Selection identical to packed-u64 shuffle-max: max fkey, ties -> smaller index.
__device__ __forceinline__ void top32_of_256(
    const float* __restrict__ d, int lane, unsigned long long* __restrict__ sm,
    float& selv, int& seli)
{
    unsigned long long k[8];
#pragma unroll
    for (int r = 0; r < 8; r++) {
        int n = r * 32 + lane;
        k[r] = (((unsigned long long)fkey(d[n])) << 32) | (unsigned int)(~(unsigned int)n);
    }
    SORT8_DESC();
#pragma unroll
    for (int r = 0; r < 8; r++) sm[lane * 8 + r] = k[r];
    __syncwarp();

    int ptr = 0;
    float sv = 0.f; int si = 0;
    for (int i = 0; i < 32; i++) {
        unsigned long long h = (ptr < 8) ? sm[lane * 8 + ptr] : 0ULL;
        unsigned int hk = (unsigned int)(h >> 32);
        unsigned int vmax = __reduce_max_sync(0xFFFFFFFFu, hk);
        unsigned int n = ~(unsigned int)h;                       // original index (valid when h!=0)
        unsigned int aux = (hk == vmax) ? (256u - n) : 0u;       // max aux <=> min n among tied
        unsigned int amax = __reduce_max_sync(0xFFFFFFFFu, aux);
        unsigned int wn = 256u - amax;                           // winning index; lane = wn&31
        if (lane == (int)(wn & 31u)) ptr++;
        if (lane == i) { sv = finv(vmax); si = (int)wn; }
    }
    __syncwarp();
    selv = sv; seli = si;
}

// block = one token, 8 warps: warps 0-3 extract p=0 (per head), warps 4-7 extract p=1,
// then warps 0-3 merge + softmax + write.
__global__ __launch_bounds__(256) void topk_kernel(
    const float* __restrict__ dots, float* __restrict__ wout, int* __restrict__ vout)
{
    const int token = blockIdx.x;
    const int wid = threadIdx.x >> 5;       // 0..7
    const int lane = threadIdx.x & 31;
    const int h = wid & 3;                   // head
    const bool isY = wid >= 4;               // p=1 extractor warps

    __shared__ unsigned long long ssm[8][256];
    __shared__ float syv_s[4][32];
    __shared__ int   syi_s[4][32];

    const float* src = dots + (size_t)token * 2048 + h * 512 + (isY ? 256 : 0);

    float v; int idx;
    top32_of_256(src, lane, ssm[wid], v, idx);

    if (isY) { syv_s[h][lane] = v; syi_s[h][lane] = idx; }
    __syncthreads();

    if (!isY) {
        const float sxv = v;  const int sxi = idx;
        const float syv = syv_s[h][lane];
        const int   syi = syi_s[h][lane];

        // top-32 of the 32x32 sum matrix sx[i]+sy[j]; lane = column j, per-lane frontier pj.
        int pj = 0;
        float fsv = 0.f; int fvidx = 0;
        for (int i = 0; i < 32; i++) {
            int srcl = (pj < 32) ? pj : 31;
            float sxp = __shfl_sync(0xFFFFFFFFu, sxv, srcl);
            float cand = __fadd_rn(sxp, syv);
            unsigned int ck = (pj < 32) ? fkey(cand) : 0u;
            unsigned int vmax = __reduce_max_sync(0xFFFFFFFFu, ck);
            unsigned int flat = (unsigned int)(pj * 32 + lane);        // reshape order i*32+j
            unsigned int aux = (ck == vmax) ? (1024u - flat) : 0u;      // min flat among tied
            unsigned int amax = __reduce_max_sync(0xFFFFFFFFu, aux);
            unsigned int wf = 1024u - amax;
            int wi = (int)(wf >> 5), wj = (int)(wf & 31u);
            int ixv = __shfl_sync(0xFFFFFFFFu, sxi, wi);
            int iyv = __shfl_sync(0xFFFFFFFFu, syi, wj);
            if (lane == wj) pj++;
            if (lane == i) { fsv = finv(vmax); fvidx = ixv * 256 + iyv; }
        }

        // softmax over the 32 selected (lane 0 holds the max: first extracted)
        const float mx = __shfl_sync(0xFFFFFFFFu, fsv, 0);
        const float e = expf(__fadd_rn(fsv, -mx));
        float ssum = e;
#pragma unroll
        for (int off = 16; off; off >>= 1) ssum += __shfl_xor_sync(0xFFFFFFFFu, ssum, off);
        const float w = __fdiv_rn(e, ssum);

        const int base = (token * 4 + h) * 32 + lane;
        wout[base] = w;
        vout[base] = fvidx;
    }
}

// =================== weighted gather: ascending fused chain ===================
__global__ __launch_bounds__(128) void gather_kernel(
    const float* __restrict__ values, const float* __restrict__ w,
    const int* __restrict__ vidx, float* __restrict__ out)
{
    const int token = blockIdx.x;
    const int t = threadIdx.x;
    __shared__ float sw[128];
    __shared__ int   si[128];
    sw[t] = w[(size_t)token * 128 + t];
    si[t] = vidx[(size_t)token * 128 + t];
    __syncthreads();

    float4 acc = make_float4(0.f, 0.f, 0.f, 0.f);
#pragma unroll 8
    for (int r = 0; r < 128; r++) {
        const float4* row = (const float4*)(values + (size_t)si[r] * 512);
        float4 v = __ldg(&row[t]);
        float wr = sw[r];
        acc.x = fmaf(wr, v.x, acc.x); acc.y = fmaf(wr, v.y, acc.y);
        acc.z = fmaf(wr, v.z, acc.z); acc.w = fmaf(wr, v.w, acc.w);
    }
    ((float4*)(out + (size_t)token * 512))[t] = acc;
}

// =================== launcher ===================
extern "C" void kernel_launch(void* const* d_in, const int* in_sizes, int n_in,
                              void* d_out, int out_size)
{
    const float* x      = (const float*)d_in[0];   // (2,2048,512)
    const float* wq     = (const float*)d_in[1];   // (1024,512)
    const float* ln_g   = (const float*)d_in[2];   // (128,)
    const float* ln_b   = (const float*)d_in[3];   // (128,)
    const float* keys   = (const float*)d_in[4];   // (4,256,2,128)
    const float* values = (const float*)d_in[5];   // (65536,512)
    float* out = (float*)d_out;

    float *qp, *dp, *wp; int* ip;
    cudaGetSymbolAddress((void**)&qp, g_q);
    cudaGetSymbolAddress((void**)&dp, g_dots);
    cudaGetSymbolAddress((void**)&wp, g_w);
    cudaGetSymbolAddress((void**)&ip, g_vidx);

    // 1) q = x @ wq^T : ascending fused chain, 128x128 tiles
    gemm_asc_128<<<dim3(DQ / QBN, TOK / QBM), 256>>>(x, DIMV, wq, DIMV, qp, DQ, DIMV);

    // 2) layernorm per 128-vector (in place)
    ln_kernel<<<(TOK * 8) / LN_ROWS, LN_ROWS>>>(qp, ln_g, ln_b);

    // 3) dots: all 8 (h,p) slices in one launch, 4 k-strided chains
    gemm_dots_s4<<<dim3(NKEY / BN, TOK / BM, 8), 256>>>(qp, keys, dp);

    // 4) top-k + combine + softmax (8 warps/token, REDUX extraction)
    topk_kernel<<<TOK, 256>>>(dp, wp, ip);

    // 5) weighted value gather
    gather_kernel<<<TOK, 128>>>(values, wp, ip, out);
}